// round 1
// baseline (speedup 1.0000x reference)
#include <cuda_runtime.h>
#include <cuda_bf16.h>
#include <math.h>

// Problem constants
#define NSTEP 8
#define DSTEP 128
#define NEMBD 1024
#define VOCAB 50257
#define BB 2
#define TT 2039
#define KK 2048          // K = T + 2*NSTEP - (NSTEP-1)
#define MROWS (BB*KK)    // 4096
#define PRED_ROWS (BB*TT) // 4078
#define EMB_ELEMS (BB*(KK-1)*NEMBD) // 2*2047*1024

// Scratch (static device globals — no allocation allowed)
__device__ float g_x[MROWS * NEMBD];     // 16 MB
__device__ float g_newx[MROWS * NEMBD];  // 16 MB
__device__ double g_acc[2];              // [0]=nll sum, [1]=emb sq sum

// ---------------------------------------------------------------------------
__global__ void zero_acc_kernel() {
    g_acc[0] = 0.0;
    g_acc[1] = 0.0;
}

// ---------------------------------------------------------------------------
// Build x[b,k,e] = tilted + wpe
__global__ __launch_bounds__(256) void build_x_kernel(
    const float* __restrict__ noise,       // (2,2039,8,128)
    const float* __restrict__ left_noise,  // (2,8,8,128)
    const float* __restrict__ right_noise, // (2,8,8,128)
    const float* __restrict__ wte,         // (50257,128)
    const float* __restrict__ wpe,         // (2048,1024)
    const int*   __restrict__ toks)        // (2,2039)
{
    int idx = blockIdx.x * 256 + threadIdx.x;  // over 4096*1024
    int e  = idx & (NEMBD - 1);
    int bk = idx >> 10;
    int k  = bk & (KK - 1);
    int b  = bk >> 11;
    int r  = e >> 7;
    int d  = e & (DSTEP - 1);
    int s  = k + r;

    float v;
    if (s < NSTEP) {
        v = left_noise[((b * NSTEP + s) * NSTEP + r) * DSTEP + d];
    } else if (s >= NSTEP + TT) {
        v = right_noise[((b * NSTEP + (s - NSTEP - TT)) * NSTEP + r) * DSTEP + d];
    } else {
        int t = s - NSTEP;
        float w = (float)(r + 1) * 0.125f;
        int tok = toks[b * TT + t];
        float emb = wte[(size_t)tok * DSTEP + d];
        float nz  = noise[(((size_t)b * TT + t) * NSTEP + r) * DSTEP + d];
        v = emb * (1.0f - w) + nz * w;
    }
    g_x[idx] = v + wpe[k * NEMBD + e];
}

// ---------------------------------------------------------------------------
// GEMM1: new_x = tanh(x @ W_bb),  (4096,1024)@(1024,1024)
// Tile 128x128x32, 256 threads, 8x8 per thread.
__global__ __launch_bounds__(256) void gemm1_tanh_kernel(
    const float* __restrict__ W)  // (1024,1024) row-major [d][e]
{
    __shared__ float As[32][128];   // [kk][m]
    __shared__ float Bs[32][128];   // [kk][n]
    const int bm = blockIdx.y * 128;
    const int bn = blockIdx.x * 128;
    const int tid = threadIdx.x;
    const int tx = tid & 15, ty = tid >> 4;

    float acc[8][8];
#pragma unroll
    for (int i = 0; i < 8; i++)
#pragma unroll
        for (int j = 0; j < 8; j++) acc[i][j] = 0.f;

    for (int k0 = 0; k0 < NEMBD; k0 += 32) {
#pragma unroll
        for (int i = tid; i < 128 * 8; i += 256) {
            int m = i >> 3, kq = i & 7;
            float4 v = *(const float4*)&g_x[(size_t)(bm + m) * NEMBD + k0 + kq * 4];
            As[kq * 4 + 0][m] = v.x; As[kq * 4 + 1][m] = v.y;
            As[kq * 4 + 2][m] = v.z; As[kq * 4 + 3][m] = v.w;
        }
#pragma unroll
        for (int i = tid; i < 32 * 32; i += 256) {
            int kk = i >> 5, nq = i & 31;
            *(float4*)&Bs[kk][nq * 4] =
                *(const float4*)&W[(size_t)(k0 + kk) * NEMBD + bn + nq * 4];
        }
        __syncthreads();
#pragma unroll
        for (int kk = 0; kk < 32; kk++) {
            float4 a0 = *(const float4*)&As[kk][ty * 8];
            float4 a1 = *(const float4*)&As[kk][ty * 8 + 4];
            float4 b0 = *(const float4*)&Bs[kk][tx * 8];
            float4 b1 = *(const float4*)&Bs[kk][tx * 8 + 4];
            float a[8] = {a0.x, a0.y, a0.z, a0.w, a1.x, a1.y, a1.z, a1.w};
            float bb[8] = {b0.x, b0.y, b0.z, b0.w, b1.x, b1.y, b1.z, b1.w};
#pragma unroll
            for (int i = 0; i < 8; i++)
#pragma unroll
                for (int j = 0; j < 8; j++)
                    acc[i][j] = fmaf(a[i], bb[j], acc[i][j]);
        }
        __syncthreads();
    }
#pragma unroll
    for (int i = 0; i < 8; i++) {
        int m = bm + ty * 8 + i;
#pragma unroll
        for (int j = 0; j < 8; j += 4) {
            float4 v = make_float4(tanhf(acc[i][j + 0]), tanhf(acc[i][j + 1]),
                                   tanhf(acc[i][j + 2]), tanhf(acc[i][j + 3]));
            *(float4*)&g_newx[(size_t)m * NEMBD + bn + tx * 8 + j] = v;
        }
    }
}

// ---------------------------------------------------------------------------
// GEMM2: logits[m][v] = sum_d newx[m][d] * wte[v][d]   (M=4096, N=50257, K=128)
__global__ __launch_bounds__(256) void gemm2_kernel(
    const float* __restrict__ WTE,  // (50257,128)
    float* __restrict__ OUT)        // (4096,50257)
{
    __shared__ float As[32][128];   // [kk][m]
    __shared__ float Bs[32][128];   // [kk][n]
    const int bm = blockIdx.y * 128;
    const int bv = blockIdx.x * 128;
    const int tid = threadIdx.x;
    const int tx = tid & 15, ty = tid >> 4;

    float acc[8][8];
#pragma unroll
    for (int i = 0; i < 8; i++)
#pragma unroll
        for (int j = 0; j < 8; j++) acc[i][j] = 0.f;

    for (int k0 = 0; k0 < 128; k0 += 32) {
#pragma unroll
        for (int i = tid; i < 128 * 8; i += 256) {
            int m = i >> 3, kq = i & 7;
            float4 v = *(const float4*)&g_newx[(size_t)(bm + m) * NEMBD + k0 + kq * 4];
            As[kq * 4 + 0][m] = v.x; As[kq * 4 + 1][m] = v.y;
            As[kq * 4 + 2][m] = v.z; As[kq * 4 + 3][m] = v.w;
        }
#pragma unroll
        for (int i = tid; i < 128 * 8; i += 256) {
            int n = i >> 3, kq = i & 7;
            int vrow = bv + n;
            float4 w = make_float4(0.f, 0.f, 0.f, 0.f);
            if (vrow < VOCAB)
                w = *(const float4*)&WTE[(size_t)vrow * DSTEP + k0 + kq * 4];
            Bs[kq * 4 + 0][n] = w.x; Bs[kq * 4 + 1][n] = w.y;
            Bs[kq * 4 + 2][n] = w.z; Bs[kq * 4 + 3][n] = w.w;
        }
        __syncthreads();
#pragma unroll
        for (int kk = 0; kk < 32; kk++) {
            float4 a0 = *(const float4*)&As[kk][ty * 8];
            float4 a1 = *(const float4*)&As[kk][ty * 8 + 4];
            float4 b0 = *(const float4*)&Bs[kk][tx * 8];
            float4 b1 = *(const float4*)&Bs[kk][tx * 8 + 4];
            float a[8] = {a0.x, a0.y, a0.z, a0.w, a1.x, a1.y, a1.z, a1.w};
            float bb[8] = {b0.x, b0.y, b0.z, b0.w, b1.x, b1.y, b1.z, b1.w};
#pragma unroll
            for (int i = 0; i < 8; i++)
#pragma unroll
                for (int j = 0; j < 8; j++)
                    acc[i][j] = fmaf(a[i], bb[j], acc[i][j]);
        }
        __syncthreads();
    }
#pragma unroll
    for (int i = 0; i < 8; i++) {
        int m = bm + ty * 8 + i;
        size_t rowoff = (size_t)m * VOCAB;
#pragma unroll
        for (int j = 0; j < 8; j++) {
            int v = bv + tx * 8 + j;
            if (v < VOCAB) OUT[rowoff + v] = acc[i][j];
        }
    }
}

// ---------------------------------------------------------------------------
// Per-row logsumexp + NLL. Logits are small (|x| <~ 3), so no max shift needed.
__global__ __launch_bounds__(256) void softmax_nll_kernel(
    const float* __restrict__ logits,  // d_out (4096,50257)
    const int*   __restrict__ toks)
{
    __shared__ float red[256];
    int row = blockIdx.x;              // 0..4077
    int b = row / TT;
    int j = row - b * TT;
    int k = j + NSTEP;
    const float* Lr = logits + ((size_t)(b * KK + k)) * VOCAB;

    float s = 0.f;
    for (int i = threadIdx.x; i < VOCAB; i += 256)
        s += __expf(Lr[i]) ;
    red[threadIdx.x] = s;
    __syncthreads();
    for (int off = 128; off > 0; off >>= 1) {
        if (threadIdx.x < off) red[threadIdx.x] += red[threadIdx.x + off];
        __syncthreads();
    }
    if (threadIdx.x == 0) {
        int tgt = toks[row];
        float nll = logf(red[0]) - Lr[tgt];
        atomicAdd(&g_acc[0], (double)nll);
    }
}

// ---------------------------------------------------------------------------
__global__ __launch_bounds__(256) void emb_loss_kernel() {
    __shared__ float red[256];
    float s = 0.f;
    const int total = EMB_ELEMS;
    for (int idx = blockIdx.x * 256 + threadIdx.x; idx < total;
         idx += gridDim.x * 256) {
        int b = idx / ((KK - 1) * NEMBD);
        int rem = idx - b * ((KK - 1) * NEMBD);
        int k = rem >> 10;
        int e = rem & (NEMBD - 1);
        size_t base = ((size_t)(b * KK + k)) * NEMBD + e;
        float d = g_newx[base] - g_newx[base + NEMBD];
        s += d * d;
    }
    red[threadIdx.x] = s;
    __syncthreads();
    for (int off = 128; off > 0; off >>= 1) {
        if (threadIdx.x < off) red[threadIdx.x] += red[threadIdx.x + off];
        __syncthreads();
    }
    if (threadIdx.x == 0) atomicAdd(&g_acc[1], (double)red[0]);
}

// ---------------------------------------------------------------------------
__global__ void finalize_kernel(float* out, long long loss_idx) {
    double loss = g_acc[0] / (double)PRED_ROWS + g_acc[1] / (double)EMB_ELEMS;
    out[loss_idx] = (float)loss;
}

// ---------------------------------------------------------------------------
extern "C" void kernel_launch(void* const* d_in, const int* in_sizes, int n_in,
                              void* d_out, int out_size) {
    const float* noise       = (const float*)d_in[0];
    const float* left_noise  = (const float*)d_in[1];
    const float* right_noise = (const float*)d_in[2];
    const float* wte         = (const float*)d_in[3];
    const float* wpe         = (const float*)d_in[4];
    const float* W_bb        = (const float*)d_in[5];
    const int*   toks        = (const int*)d_in[6];
    float* out = (float*)d_out;

    zero_acc_kernel<<<1, 1>>>();

    build_x_kernel<<<(MROWS * NEMBD) / 256, 256>>>(noise, left_noise, right_noise,
                                                   wte, wpe, toks);

    gemm1_tanh_kernel<<<dim3(NEMBD / 128, MROWS / 128), 256>>>(W_bb);

    gemm2_kernel<<<dim3((VOCAB + 127) / 128, MROWS / 128), 256>>>(wte, out);

    softmax_nll_kernel<<<PRED_ROWS, 256>>>(out, toks);

    emb_loss_kernel<<<2048, 256>>>();

    long long nlog = (long long)MROWS * VOCAB;
    if ((long long)out_size > nlog) {
        finalize_kernel<<<1, 1>>>(out, (long long)out_size - 1);
    }
}

// round 3
// speedup vs baseline: 2.1013x; 2.1013x over previous
#include <cuda_runtime.h>
#include <cuda_bf16.h>
#include <math.h>
#include <stdint.h>

// Problem constants
#define NSTEP 8
#define DSTEP 128
#define NEMBD 1024
#define VOCAB 50257
#define VPAD  50304            // 393 * 128
#define BB 2
#define TT 2039
#define KK 2048
#define MROWS (BB*KK)          // 4096
#define PRED_ROWS (BB*TT)      // 4078
#define EMB_ELEMS (BB*(KK-1)*NEMBD)

// Scratch
__device__ float g_x[MROWS * NEMBD];
__device__ float g_newx[MROWS * NEMBD];
__device__ double g_acc[2];
__device__ float g_rowsum[MROWS];
__device__ __nv_bfloat16 g_Bhi[(size_t)VPAD * DSTEP];
__device__ __nv_bfloat16 g_Blo[(size_t)VPAD * DSTEP];
__device__ __nv_bfloat16 g_Ahi[(size_t)MROWS * DSTEP];
__device__ __nv_bfloat16 g_Alo[(size_t)MROWS * DSTEP];

__device__ __forceinline__ uint32_t smem_u32(const void* p) {
    uint32_t a;
    asm("{ .reg .u64 t; cvta.to.shared.u64 t, %1; cvt.u32.u64 %0, t; }"
        : "=r"(a) : "l"(p));
    return a;
}

// ---------------------------------------------------------------------------
__global__ __launch_bounds__(256) void zero_kernel() {
    int i = blockIdx.x * 256 + threadIdx.x;
    if (i == 0) { g_acc[0] = 0.0; g_acc[1] = 0.0; }
    if (i < MROWS) g_rowsum[i] = 0.f;
}

// ---------------------------------------------------------------------------
__global__ __launch_bounds__(256) void build_x_kernel(
    const float* __restrict__ noise, const float* __restrict__ left_noise,
    const float* __restrict__ right_noise, const float* __restrict__ wte,
    const float* __restrict__ wpe, const int* __restrict__ toks)
{
    int idx = blockIdx.x * 256 + threadIdx.x;
    int e  = idx & (NEMBD - 1);
    int bk = idx >> 10;
    int k  = bk & (KK - 1);
    int b  = bk >> 11;
    int r  = e >> 7;
    int d  = e & (DSTEP - 1);
    int s  = k + r;

    float v;
    if (s < NSTEP) {
        v = left_noise[((b * NSTEP + s) * NSTEP + r) * DSTEP + d];
    } else if (s >= NSTEP + TT) {
        v = right_noise[((b * NSTEP + (s - NSTEP - TT)) * NSTEP + r) * DSTEP + d];
    } else {
        int t = s - NSTEP;
        float w = (float)(r + 1) * 0.125f;
        int tok = toks[b * TT + t];
        float emb = wte[(size_t)tok * DSTEP + d];
        float nz  = noise[(((size_t)b * TT + t) * NSTEP + r) * DSTEP + d];
        v = emb * (1.0f - w) + nz * w;
    }
    g_x[idx] = v + wpe[k * NEMBD + e];
}

// ---------------------------------------------------------------------------
// GEMM1: new_x = tanh(x @ W_bb)   (fp32 SIMT, 128x128x32 tile)
__global__ __launch_bounds__(256) void gemm1_tanh_kernel(const float* __restrict__ W)
{
    __shared__ float As[32][128];
    __shared__ float Bs[32][128];
    const int bm = blockIdx.y * 128;
    const int bn = blockIdx.x * 128;
    const int tid = threadIdx.x;
    const int tx = tid & 15, ty = tid >> 4;

    float acc[8][8];
#pragma unroll
    for (int i = 0; i < 8; i++)
#pragma unroll
        for (int j = 0; j < 8; j++) acc[i][j] = 0.f;

    for (int k0 = 0; k0 < NEMBD; k0 += 32) {
#pragma unroll
        for (int i = tid; i < 128 * 8; i += 256) {
            int m = i >> 3, kq = i & 7;
            float4 v = *(const float4*)&g_x[(size_t)(bm + m) * NEMBD + k0 + kq * 4];
            As[kq * 4 + 0][m] = v.x; As[kq * 4 + 1][m] = v.y;
            As[kq * 4 + 2][m] = v.z; As[kq * 4 + 3][m] = v.w;
        }
#pragma unroll
        for (int i = tid; i < 32 * 32; i += 256) {
            int kk = i >> 5, nq = i & 31;
            *(float4*)&Bs[kk][nq * 4] =
                *(const float4*)&W[(size_t)(k0 + kk) * NEMBD + bn + nq * 4];
        }
        __syncthreads();
#pragma unroll
        for (int kk = 0; kk < 32; kk++) {
            float4 a0 = *(const float4*)&As[kk][ty * 8];
            float4 a1 = *(const float4*)&As[kk][ty * 8 + 4];
            float4 b0 = *(const float4*)&Bs[kk][tx * 8];
            float4 b1 = *(const float4*)&Bs[kk][tx * 8 + 4];
            float a[8] = {a0.x, a0.y, a0.z, a0.w, a1.x, a1.y, a1.z, a1.w};
            float bb[8] = {b0.x, b0.y, b0.z, b0.w, b1.x, b1.y, b1.z, b1.w};
#pragma unroll
            for (int i = 0; i < 8; i++)
#pragma unroll
                for (int j = 0; j < 8; j++)
                    acc[i][j] = fmaf(a[i], bb[j], acc[i][j]);
        }
        __syncthreads();
    }
#pragma unroll
    for (int i = 0; i < 8; i++) {
        int m = bm + ty * 8 + i;
#pragma unroll
        for (int j = 0; j < 8; j += 4) {
            float4 v = make_float4(tanhf(acc[i][j + 0]), tanhf(acc[i][j + 1]),
                                   tanhf(acc[i][j + 2]), tanhf(acc[i][j + 3]));
            *(float4*)&g_newx[(size_t)m * NEMBD + bn + tx * 8 + j] = v;
        }
    }
}

// ---------------------------------------------------------------------------
__global__ __launch_bounds__(256) void conv_wte_kernel(const float* __restrict__ wte)
{
    size_t idx = (size_t)blockIdx.x * 256 + threadIdx.x;
    size_t row = idx >> 7;
    float w = (row < VOCAB) ? wte[idx] : 0.f;
    __nv_bfloat16 hi = __float2bfloat16(w);
    __nv_bfloat16 lo = __float2bfloat16(w - __bfloat162float(hi));
    g_Bhi[idx] = hi;
    g_Blo[idx] = lo;
}

__global__ __launch_bounds__(256) void conv_A_kernel()
{
    int idx = blockIdx.x * 256 + threadIdx.x;
    int m = idx >> 7, d = idx & 127;
    float x = g_newx[(size_t)m * NEMBD + d];
    __nv_bfloat16 hi = __float2bfloat16(x);
    __nv_bfloat16 lo = __float2bfloat16(x - __bfloat162float(hi));
    g_Ahi[idx] = hi;
    g_Alo[idx] = lo;
}

// ---------------------------------------------------------------------------
// GEMM2 via mma.sync bf16 (HMMA): logits = Ahi*Bhi^T + Alo*Bhi^T + Ahi*Blo^T
// Block tile 128x128, full K=128 in SMEM. 8 warps: 4 (M) x 2 (N), warp 32x64.
// Fused per-row sum(exp(logit)) accumulated into g_rowsum.
#define ROWP 136                    // padded row: 136 bf16 = 272 B
#define TILEB (128 * ROWP * 2)      // 34816 B per tile
#define G2_SMEM (4 * TILEB)         // 139264 B

__device__ __forceinline__ void ldsm_x4(uint32_t* r, uint32_t addr) {
    asm volatile("ldmatrix.sync.aligned.m8n8.x4.shared.b16 {%0,%1,%2,%3}, [%4];"
                 : "=r"(r[0]), "=r"(r[1]), "=r"(r[2]), "=r"(r[3]) : "r"(addr));
}
__device__ __forceinline__ void mma16816(float* c, const uint32_t* a,
                                         uint32_t b0, uint32_t b1) {
    asm volatile("mma.sync.aligned.m16n8k16.row.col.f32.bf16.bf16.f32 "
                 "{%0,%1,%2,%3}, {%4,%5,%6,%7}, {%8,%9}, {%0,%1,%2,%3};"
                 : "+f"(c[0]), "+f"(c[1]), "+f"(c[2]), "+f"(c[3])
                 : "r"(a[0]), "r"(a[1]), "r"(a[2]), "r"(a[3]), "r"(b0), "r"(b1));
}

__global__ __launch_bounds__(256, 1) void gemm2_mma_kernel(float* __restrict__ OUT)
{
    extern __shared__ char smem[];
    const uint32_t sb = smem_u32(smem);
    const uint32_t s_ah = sb;
    const uint32_t s_al = sb + TILEB;
    const uint32_t s_bh = sb + 2 * TILEB;
    const uint32_t s_bl = sb + 3 * TILEB;

    const int tid = threadIdx.x;
    const int w = tid >> 5, lane = tid & 31;
    const int bm = blockIdx.y * 128;
    const int bv = blockIdx.x * 128;

    // ---- load 4 tiles (128 rows x 128 bf16) into padded row-major SMEM ----
    {
        const __nv_bfloat16* srcs[4] = {
            g_Ahi + (size_t)bm * DSTEP, g_Alo + (size_t)bm * DSTEP,
            g_Bhi + (size_t)bv * DSTEP, g_Blo + (size_t)bv * DSTEP };
#pragma unroll
        for (int rgn = 0; rgn < 4; rgn++) {
            const uint4* src = (const uint4*)srcs[rgn];
            uint32_t dst = sb + rgn * TILEB;
#pragma unroll
            for (int i = tid; i < 2048; i += 256) {
                int row = i >> 4, ch = i & 15;
                uint4 v = src[row * 16 + ch];
                uint32_t a = dst + row * (ROWP * 2) + ch * 16;
                asm volatile("st.shared.v4.b32 [%0], {%1,%2,%3,%4};"
                             :: "r"(a), "r"(v.x), "r"(v.y), "r"(v.z), "r"(v.w)
                             : "memory");
            }
        }
    }
    __syncthreads();

    // ---- per-thread ldmatrix addresses ----
    const int warpM0 = (w & 3) * 32;
    const int warpN0 = (w >> 2) * 64;
    const int qr = lane & 7, sel = lane >> 3;

    // A: matrices (m-low klow, m-high klow, m-low khigh, m-high khigh)
    uint32_t aoff[2];
#pragma unroll
    for (int mi = 0; mi < 2; mi++) {
        int row = warpM0 + mi * 16 + qr + (sel & 1) * 8;
        int col = (sel >> 1) * 8;
        aoff[mi] = row * (ROWP * 2) + col * 2;
    }
    // B pair p covers n-tiles 2p,2p+1: (n-low klow, n-low khigh, n-high klow, n-high khigh)
    uint32_t boff[4];
#pragma unroll
    for (int p = 0; p < 4; p++) {
        int row = warpN0 + p * 16 + qr + (sel >> 1) * 8;
        int col = (sel & 1) * 8;
        boff[p] = row * (ROWP * 2) + col * 2;
    }

    float acc[2][8][4];
#pragma unroll
    for (int mi = 0; mi < 2; mi++)
#pragma unroll
        for (int ni = 0; ni < 8; ni++)
#pragma unroll
            for (int q = 0; q < 4; q++) acc[mi][ni][q] = 0.f;

    const uint32_t abase[3] = { s_ah, s_al, s_ah };
    const uint32_t bbase[3] = { s_bh, s_bh, s_bl };

#pragma unroll
    for (int prod = 0; prod < 3; prod++) {
        uint32_t ab = abase[prod], bb = bbase[prod];
#pragma unroll
        for (int ks = 0; ks < 8; ks++) {
            uint32_t koff = ks * 32;  // 16 bf16 = 32 B
            uint32_t af[2][4], bf[4][4];
#pragma unroll
            for (int mi = 0; mi < 2; mi++) ldsm_x4(af[mi], ab + aoff[mi] + koff);
#pragma unroll
            for (int p = 0; p < 4; p++) ldsm_x4(bf[p], bb + boff[p] + koff);
#pragma unroll
            for (int mi = 0; mi < 2; mi++)
#pragma unroll
                for (int nt = 0; nt < 8; nt++) {
                    uint32_t b0 = bf[nt >> 1][(nt & 1) * 2];
                    uint32_t b1 = bf[nt >> 1][(nt & 1) * 2 + 1];
                    mma16816(acc[mi][nt], af[mi], b0, b1);
                }
        }
    }

    // ---- epilogue: store logits + fused per-row exp-sum ----
    const int r = lane >> 2, c2 = (lane & 3) * 2;
    float rsum[2][2] = {{0.f, 0.f}, {0.f, 0.f}};

#pragma unroll
    for (int mi = 0; mi < 2; mi++) {
        int mb = bm + warpM0 + mi * 16;
        int m0 = mb + r, m1 = mb + r + 8;
        size_t ro0 = (size_t)m0 * VOCAB, ro1 = (size_t)m1 * VOCAB;
#pragma unroll
        for (int ni = 0; ni < 8; ni++) {
            int n0 = bv + warpN0 + ni * 8 + c2;
            bool v0 = n0 < VOCAB, v1 = (n0 + 1) < VOCAB;
            float c00 = acc[mi][ni][0], c01 = acc[mi][ni][1];
            float c10 = acc[mi][ni][2], c11 = acc[mi][ni][3];
            if (v0) { OUT[ro0 + n0] = c00; OUT[ro1 + n0] = c10; }
            if (v1) { OUT[ro0 + n0 + 1] = c01; OUT[ro1 + n0 + 1] = c11; }
            rsum[mi][0] += (v0 ? __expf(c00) : 0.f) + (v1 ? __expf(c01) : 0.f);
            rsum[mi][1] += (v0 ? __expf(c10) : 0.f) + (v1 ? __expf(c11) : 0.f);
        }
    }
#pragma unroll
    for (int mi = 0; mi < 2; mi++)
#pragma unroll
        for (int h = 0; h < 2; h++) {
            float s = rsum[mi][h];
            s += __shfl_xor_sync(0xFFFFFFFF, s, 1);
            s += __shfl_xor_sync(0xFFFFFFFF, s, 2);
            if ((lane & 3) == 0) {
                int m = bm + warpM0 + mi * 16 + r + h * 8;
                atomicAdd(&g_rowsum[m], s);
            }
        }
}

// ---------------------------------------------------------------------------
// NLL from fused row sums: nll = log(sum_exp) - logit[tgt]
__global__ __launch_bounds__(256) void nll_kernel(
    const float* __restrict__ logits, const int* __restrict__ toks)
{
    __shared__ float red[256];
    int row = blockIdx.x * 256 + threadIdx.x;
    float nll = 0.f;
    if (row < PRED_ROWS) {
        int b = row / TT;
        int j = row - b * TT;
        int m = b * KK + j + NSTEP;
        int tgt = toks[row];
        nll = logf(g_rowsum[m]) - logits[(size_t)m * VOCAB + tgt];
    }
    red[threadIdx.x] = nll;
    __syncthreads();
    for (int off = 128; off > 0; off >>= 1) {
        if (threadIdx.x < off) red[threadIdx.x] += red[threadIdx.x + off];
        __syncthreads();
    }
    if (threadIdx.x == 0) atomicAdd(&g_acc[0], (double)red[0]);
}

// ---------------------------------------------------------------------------
__global__ __launch_bounds__(256) void emb_loss_kernel() {
    __shared__ float red[256];
    float s = 0.f;
    const int total = EMB_ELEMS;
    for (int idx = blockIdx.x * 256 + threadIdx.x; idx < total;
         idx += gridDim.x * 256) {
        int b = idx / ((KK - 1) * NEMBD);
        int rem = idx - b * ((KK - 1) * NEMBD);
        int k = rem >> 10;
        int e = rem & (NEMBD - 1);
        size_t base = ((size_t)(b * KK + k)) * NEMBD + e;
        float d = g_newx[base] - g_newx[base + NEMBD];
        s += d * d;
    }
    red[threadIdx.x] = s;
    __syncthreads();
    for (int off = 128; off > 0; off >>= 1) {
        if (threadIdx.x < off) red[threadIdx.x] += red[threadIdx.x + off];
        __syncthreads();
    }
    if (threadIdx.x == 0) atomicAdd(&g_acc[1], (double)red[0]);
}

// ---------------------------------------------------------------------------
__global__ void finalize_kernel(float* out, long long loss_idx) {
    double loss = g_acc[0] / (double)PRED_ROWS + g_acc[1] / (double)EMB_ELEMS;
    out[loss_idx] = (float)loss;
}

// ---------------------------------------------------------------------------
extern "C" void kernel_launch(void* const* d_in, const int* in_sizes, int n_in,
                              void* d_out, int out_size) {
    const float* noise       = (const float*)d_in[0];
    const float* left_noise  = (const float*)d_in[1];
    const float* right_noise = (const float*)d_in[2];
    const float* wte         = (const float*)d_in[3];
    const float* wpe         = (const float*)d_in[4];
    const float* W_bb        = (const float*)d_in[5];
    const int*   toks        = (const int*)d_in[6];
    float* out = (float*)d_out;

    static int smem_set = 0;
    if (!smem_set) {
        cudaFuncSetAttribute(gemm2_mma_kernel,
                             cudaFuncAttributeMaxDynamicSharedMemorySize, G2_SMEM);
        smem_set = 1;
    }

    zero_kernel<<<MROWS / 256, 256>>>();

    build_x_kernel<<<(MROWS * NEMBD) / 256, 256>>>(noise, left_noise, right_noise,
                                                   wte, wpe, toks);

    gemm1_tanh_kernel<<<dim3(NEMBD / 128, MROWS / 128), 256>>>(W_bb);

    conv_wte_kernel<<<(VPAD * DSTEP) / 256, 256>>>(wte);
    conv_A_kernel<<<(MROWS * DSTEP) / 256, 256>>>();

    gemm2_mma_kernel<<<dim3(VPAD / 128, MROWS / 128), 256, G2_SMEM>>>(out);

    nll_kernel<<<(PRED_ROWS + 255) / 256, 256>>>(out, toks);

    emb_loss_kernel<<<2048, 256>>>();

    long long nlog = (long long)MROWS * VOCAB;
    if ((long long)out_size > nlog) {
        finalize_kernel<<<1, 1>>>(out, (long long)out_size - 1);
    }
}

// round 4
// speedup vs baseline: 2.3312x; 1.1094x over previous
#include <cuda_runtime.h>
#include <cuda_bf16.h>
#include <math.h>
#include <stdint.h>

// Problem constants
#define NSTEP 8
#define DSTEP 128
#define NEMBD 1024
#define VOCAB 50257
#define VPAD  50304            // 393 * 128
#define BB 2
#define TT 2039
#define KK 2048
#define MROWS (BB*KK)          // 4096
#define PRED_ROWS (BB*TT)      // 4078
#define EMB_ELEMS (BB*(KK-1)*NEMBD)

// Scratch
__device__ float g_newx[MROWS * NEMBD];
__device__ double g_acc[2];
__device__ float g_rowsum[MROWS];
__device__ __nv_bfloat16 g_Xhi[(size_t)MROWS * NEMBD];
__device__ __nv_bfloat16 g_Xlo[(size_t)MROWS * NEMBD];
__device__ __nv_bfloat16 g_Whi[(size_t)NEMBD * NEMBD];  // transposed [e][d]
__device__ __nv_bfloat16 g_Wlo[(size_t)NEMBD * NEMBD];
__device__ __nv_bfloat16 g_Bhi[(size_t)VPAD * DSTEP];
__device__ __nv_bfloat16 g_Blo[(size_t)VPAD * DSTEP];
__device__ __nv_bfloat16 g_Ahi[(size_t)MROWS * DSTEP];
__device__ __nv_bfloat16 g_Alo[(size_t)MROWS * DSTEP];

__device__ __forceinline__ uint32_t smem_u32(const void* p) {
    uint32_t a;
    asm("{ .reg .u64 t; cvta.to.shared.u64 t, %1; cvt.u32.u64 %0, t; }"
        : "=r"(a) : "l"(p));
    return a;
}

// ---------------------------------------------------------------------------
__global__ __launch_bounds__(256) void zero_kernel() {
    int i = blockIdx.x * 256 + threadIdx.x;
    if (i == 0) { g_acc[0] = 0.0; g_acc[1] = 0.0; }
    if (i < MROWS) g_rowsum[i] = 0.f;
}

// ---------------------------------------------------------------------------
// Build x in bf16 hi/lo directly.
__global__ __launch_bounds__(256) void build_x_kernel(
    const float* __restrict__ noise, const float* __restrict__ left_noise,
    const float* __restrict__ right_noise, const float* __restrict__ wte,
    const float* __restrict__ wpe, const int* __restrict__ toks)
{
    int idx = blockIdx.x * 256 + threadIdx.x;
    int e  = idx & (NEMBD - 1);
    int bk = idx >> 10;
    int k  = bk & (KK - 1);
    int b  = bk >> 11;
    int r  = e >> 7;
    int d  = e & (DSTEP - 1);
    int s  = k + r;

    float v;
    if (s < NSTEP) {
        v = left_noise[((b * NSTEP + s) * NSTEP + r) * DSTEP + d];
    } else if (s >= NSTEP + TT) {
        v = right_noise[((b * NSTEP + (s - NSTEP - TT)) * NSTEP + r) * DSTEP + d];
    } else {
        int t = s - NSTEP;
        float w = (float)(r + 1) * 0.125f;
        int tok = toks[b * TT + t];
        float emb = wte[(size_t)tok * DSTEP + d];
        float nz  = noise[(((size_t)b * TT + t) * NSTEP + r) * DSTEP + d];
        v = emb * (1.0f - w) + nz * w;
    }
    v += wpe[k * NEMBD + e];
    __nv_bfloat16 hi = __float2bfloat16(v);
    g_Xhi[idx] = hi;
    g_Xlo[idx] = __float2bfloat16(v - __bfloat162float(hi));
}

// ---------------------------------------------------------------------------
// Transpose W_bb -> [e][d] + split hi/lo.
__global__ __launch_bounds__(256) void conv_W_kernel(const float* __restrict__ W)
{
    __shared__ float t[32][33];
    int be = blockIdx.x * 32;   // output row block (e)
    int bd = blockIdx.y * 32;   // output col block (d)
    int tx = threadIdx.x & 31, ty = threadIdx.x >> 5;  // 32 x 8
#pragma unroll
    for (int i = 0; i < 32; i += 8)
        t[ty + i][tx] = W[(size_t)(bd + ty + i) * NEMBD + be + tx]; // t[d'][e']
    __syncthreads();
#pragma unroll
    for (int i = 0; i < 32; i += 8) {
        float v = t[tx][ty + i];          // W[bd+tx][be+ty+i]
        __nv_bfloat16 hi = __float2bfloat16(v);
        size_t o = (size_t)(be + ty + i) * NEMBD + bd + tx;
        g_Whi[o] = hi;
        g_Wlo[o] = __float2bfloat16(v - __bfloat162float(hi));
    }
}

// ---------------------------------------------------------------------------
__global__ __launch_bounds__(256) void conv_wte_kernel(const float* __restrict__ wte)
{
    size_t idx = (size_t)blockIdx.x * 256 + threadIdx.x;
    size_t row = idx >> 7;
    float w = (row < VOCAB) ? wte[idx] : 0.f;
    __nv_bfloat16 hi = __float2bfloat16(w);
    g_Bhi[idx] = hi;
    g_Blo[idx] = __float2bfloat16(w - __bfloat162float(hi));
}

// ---------------------------------------------------------------------------
// Shared MMA helpers
#define ROWP 136
#define TILEB (128 * ROWP * 2)      // 34816 B
#define MMA_SMEM (4 * TILEB)        // 139264 B

__device__ __forceinline__ void ldsm_x4(uint32_t* r, uint32_t addr) {
    asm volatile("ldmatrix.sync.aligned.m8n8.x4.shared.b16 {%0,%1,%2,%3}, [%4];"
                 : "=r"(r[0]), "=r"(r[1]), "=r"(r[2]), "=r"(r[3]) : "r"(addr));
}
__device__ __forceinline__ void mma16816(float* c, const uint32_t* a,
                                         uint32_t b0, uint32_t b1) {
    asm volatile("mma.sync.aligned.m16n8k16.row.col.f32.bf16.bf16.f32 "
                 "{%0,%1,%2,%3}, {%4,%5,%6,%7}, {%8,%9}, {%0,%1,%2,%3};"
                 : "+f"(c[0]), "+f"(c[1]), "+f"(c[2]), "+f"(c[3])
                 : "r"(a[0]), "r"(a[1]), "r"(a[2]), "r"(a[3]), "r"(b0), "r"(b1));
}

// Load a 128x128 bf16 tile (row stride src_stride bf16) into padded SMEM.
__device__ __forceinline__ void load_tile(uint32_t dst, const __nv_bfloat16* src,
                                          int src_stride, int tid) {
    const uint4* s = (const uint4*)src;
    int str4 = src_stride >> 3;
#pragma unroll
    for (int i = tid; i < 2048; i += 256) {
        int row = i >> 4, ch = i & 15;
        uint4 v = s[row * str4 + ch];
        uint32_t a = dst + row * (ROWP * 2) + ch * 16;
        asm volatile("st.shared.v4.b32 [%0], {%1,%2,%3,%4};"
                     :: "r"(a), "r"(v.x), "r"(v.y), "r"(v.z), "r"(v.w) : "memory");
    }
}

// ---------------------------------------------------------------------------
// GEMM1 (HMMA): new_x = tanh(Xhi*Whi^T + Xlo*Whi^T + Xhi*Wlo^T)
// Grid (8, 32); block 128x128 tile; K=1024 in 8 chunks of 128.
__global__ __launch_bounds__(256, 1) void gemm1_mma_kernel()
{
    extern __shared__ char smem[];
    const uint32_t sb = smem_u32(smem);
    const uint32_t s_ah = sb, s_al = sb + TILEB;
    const uint32_t s_bh = sb + 2 * TILEB, s_bl = sb + 3 * TILEB;

    const int tid = threadIdx.x;
    const int w = tid >> 5, lane = tid & 31;
    const int bm = blockIdx.y * 128;
    const int bn = blockIdx.x * 128;

    const int warpM0 = (w & 3) * 32;
    const int warpN0 = (w >> 2) * 64;
    const int qr = lane & 7, sel = lane >> 3;

    uint32_t aoff[2], boff[4];
#pragma unroll
    for (int mi = 0; mi < 2; mi++) {
        int row = warpM0 + mi * 16 + qr + (sel & 1) * 8;
        aoff[mi] = row * (ROWP * 2) + ((sel >> 1) * 8) * 2;
    }
#pragma unroll
    for (int p = 0; p < 4; p++) {
        int row = warpN0 + p * 16 + qr + (sel >> 1) * 8;
        boff[p] = row * (ROWP * 2) + ((sel & 1) * 8) * 2;
    }

    float acc[2][8][4];
#pragma unroll
    for (int mi = 0; mi < 2; mi++)
#pragma unroll
        for (int ni = 0; ni < 8; ni++)
#pragma unroll
            for (int q = 0; q < 4; q++) acc[mi][ni][q] = 0.f;

    for (int kc = 0; kc < NEMBD; kc += 128) {
        load_tile(s_ah, g_Xhi + (size_t)bm * NEMBD + kc, NEMBD, tid);
        load_tile(s_al, g_Xlo + (size_t)bm * NEMBD + kc, NEMBD, tid);
        load_tile(s_bh, g_Whi + (size_t)bn * NEMBD + kc, NEMBD, tid);
        load_tile(s_bl, g_Wlo + (size_t)bn * NEMBD + kc, NEMBD, tid);
        __syncthreads();

        const uint32_t abase[3] = { s_ah, s_al, s_ah };
        const uint32_t bbase[3] = { s_bh, s_bh, s_bl };
#pragma unroll
        for (int prod = 0; prod < 3; prod++) {
            uint32_t ab = abase[prod], bb = bbase[prod];
#pragma unroll
            for (int ks = 0; ks < 8; ks++) {
                uint32_t koff = ks * 32;
                uint32_t af[2][4], bf[4][4];
#pragma unroll
                for (int mi = 0; mi < 2; mi++) ldsm_x4(af[mi], ab + aoff[mi] + koff);
#pragma unroll
                for (int p = 0; p < 4; p++) ldsm_x4(bf[p], bb + boff[p] + koff);
#pragma unroll
                for (int mi = 0; mi < 2; mi++)
#pragma unroll
                    for (int nt = 0; nt < 8; nt++)
                        mma16816(acc[mi][nt], af[mi],
                                 bf[nt >> 1][(nt & 1) * 2], bf[nt >> 1][(nt & 1) * 2 + 1]);
            }
        }
        __syncthreads();
    }

    // Epilogue: tanh, write newx fp32; for global cols < 128 also write Ahi/Alo.
    const int r = lane >> 2, c2 = (lane & 3) * 2;
#pragma unroll
    for (int mi = 0; mi < 2; mi++) {
        int mb = bm + warpM0 + mi * 16;
#pragma unroll
        for (int h = 0; h < 2; h++) {
            int m = mb + r + h * 8;
#pragma unroll
            for (int ni = 0; ni < 8; ni++) {
                int n0 = bn + warpN0 + ni * 8 + c2;
                float t0 = tanhf(acc[mi][ni][h * 2 + 0]);
                float t1 = tanhf(acc[mi][ni][h * 2 + 1]);
                *(float2*)&g_newx[(size_t)m * NEMBD + n0] = make_float2(t0, t1);
                if (n0 < DSTEP) {
                    __nv_bfloat16 h0 = __float2bfloat16(t0);
                    __nv_bfloat16 h1 = __float2bfloat16(t1);
                    __nv_bfloat16 l0 = __float2bfloat16(t0 - __bfloat162float(h0));
                    __nv_bfloat16 l1 = __float2bfloat16(t1 - __bfloat162float(h1));
                    *(__nv_bfloat162*)&g_Ahi[(size_t)m * DSTEP + n0] =
                        __nv_bfloat162(h0, h1);
                    *(__nv_bfloat162*)&g_Alo[(size_t)m * DSTEP + n0] =
                        __nv_bfloat162(l0, l1);
                }
            }
        }
    }
}

// ---------------------------------------------------------------------------
// GEMM2 (HMMA): logits = Ahi*Bhi^T + Alo*Bhi^T + Ahi*Blo^T, fused exp-row-sum.
__global__ __launch_bounds__(256, 1) void gemm2_mma_kernel(float* __restrict__ OUT)
{
    extern __shared__ char smem[];
    const uint32_t sb = smem_u32(smem);
    const uint32_t s_ah = sb, s_al = sb + TILEB;
    const uint32_t s_bh = sb + 2 * TILEB, s_bl = sb + 3 * TILEB;

    const int tid = threadIdx.x;
    const int w = tid >> 5, lane = tid & 31;
    const int bm = blockIdx.y * 128;
    const int bv = blockIdx.x * 128;

    load_tile(s_ah, g_Ahi + (size_t)bm * DSTEP, DSTEP, tid);
    load_tile(s_al, g_Alo + (size_t)bm * DSTEP, DSTEP, tid);
    load_tile(s_bh, g_Bhi + (size_t)bv * DSTEP, DSTEP, tid);
    load_tile(s_bl, g_Blo + (size_t)bv * DSTEP, DSTEP, tid);
    __syncthreads();

    const int warpM0 = (w & 3) * 32;
    const int warpN0 = (w >> 2) * 64;
    const int qr = lane & 7, sel = lane >> 3;

    uint32_t aoff[2], boff[4];
#pragma unroll
    for (int mi = 0; mi < 2; mi++) {
        int row = warpM0 + mi * 16 + qr + (sel & 1) * 8;
        aoff[mi] = row * (ROWP * 2) + ((sel >> 1) * 8) * 2;
    }
#pragma unroll
    for (int p = 0; p < 4; p++) {
        int row = warpN0 + p * 16 + qr + (sel >> 1) * 8;
        boff[p] = row * (ROWP * 2) + ((sel & 1) * 8) * 2;
    }

    float acc[2][8][4];
#pragma unroll
    for (int mi = 0; mi < 2; mi++)
#pragma unroll
        for (int ni = 0; ni < 8; ni++)
#pragma unroll
            for (int q = 0; q < 4; q++) acc[mi][ni][q] = 0.f;

    const uint32_t abase[3] = { s_ah, s_al, s_ah };
    const uint32_t bbase[3] = { s_bh, s_bh, s_bl };
#pragma unroll
    for (int prod = 0; prod < 3; prod++) {
        uint32_t ab = abase[prod], bb = bbase[prod];
#pragma unroll
        for (int ks = 0; ks < 8; ks++) {
            uint32_t koff = ks * 32;
            uint32_t af[2][4], bf[4][4];
#pragma unroll
            for (int mi = 0; mi < 2; mi++) ldsm_x4(af[mi], ab + aoff[mi] + koff);
#pragma unroll
            for (int p = 0; p < 4; p++) ldsm_x4(bf[p], bb + boff[p] + koff);
#pragma unroll
            for (int mi = 0; mi < 2; mi++)
#pragma unroll
                for (int nt = 0; nt < 8; nt++)
                    mma16816(acc[mi][nt], af[mi],
                             bf[nt >> 1][(nt & 1) * 2], bf[nt >> 1][(nt & 1) * 2 + 1]);
        }
    }

    // Epilogue: store logits + fused per-row exp-sum.
    const int r = lane >> 2, c2 = (lane & 3) * 2;
    float rsum[2][2] = {{0.f, 0.f}, {0.f, 0.f}};
#pragma unroll
    for (int mi = 0; mi < 2; mi++) {
        int mb = bm + warpM0 + mi * 16;
        int m0 = mb + r, m1 = mb + r + 8;
        size_t ro0 = (size_t)m0 * VOCAB, ro1 = (size_t)m1 * VOCAB;
#pragma unroll
        for (int ni = 0; ni < 8; ni++) {
            int n0 = bv + warpN0 + ni * 8 + c2;
            bool v0 = n0 < VOCAB, v1 = (n0 + 1) < VOCAB;
            float c00 = acc[mi][ni][0], c01 = acc[mi][ni][1];
            float c10 = acc[mi][ni][2], c11 = acc[mi][ni][3];
            if (v0) { OUT[ro0 + n0] = c00; OUT[ro1 + n0] = c10; }
            if (v1) { OUT[ro0 + n0 + 1] = c01; OUT[ro1 + n0 + 1] = c11; }
            rsum[mi][0] += (v0 ? __expf(c00) : 0.f) + (v1 ? __expf(c01) : 0.f);
            rsum[mi][1] += (v0 ? __expf(c10) : 0.f) + (v1 ? __expf(c11) : 0.f);
        }
    }
#pragma unroll
    for (int mi = 0; mi < 2; mi++)
#pragma unroll
        for (int h = 0; h < 2; h++) {
            float s = rsum[mi][h];
            s += __shfl_xor_sync(0xFFFFFFFF, s, 1);
            s += __shfl_xor_sync(0xFFFFFFFF, s, 2);
            if ((lane & 3) == 0) {
                int m = bm + warpM0 + mi * 16 + r + h * 8;
                atomicAdd(&g_rowsum[m], s);
            }
        }
}

// ---------------------------------------------------------------------------
__global__ __launch_bounds__(256) void nll_kernel(
    const float* __restrict__ logits, const int* __restrict__ toks)
{
    __shared__ float red[256];
    int row = blockIdx.x * 256 + threadIdx.x;
    float nll = 0.f;
    if (row < PRED_ROWS) {
        int b = row / TT;
        int j = row - b * TT;
        int m = b * KK + j + NSTEP;
        int tgt = toks[row];
        nll = logf(g_rowsum[m]) - logits[(size_t)m * VOCAB + tgt];
    }
    red[threadIdx.x] = nll;
    __syncthreads();
    for (int off = 128; off > 0; off >>= 1) {
        if (threadIdx.x < off) red[threadIdx.x] += red[threadIdx.x + off];
        __syncthreads();
    }
    if (threadIdx.x == 0) atomicAdd(&g_acc[0], (double)red[0]);
}

// ---------------------------------------------------------------------------
__global__ __launch_bounds__(256) void emb_loss_kernel() {
    __shared__ float red[256];
    float s = 0.f;
    const int total = EMB_ELEMS;
    for (int idx = blockIdx.x * 256 + threadIdx.x; idx < total;
         idx += gridDim.x * 256) {
        int b = idx / ((KK - 1) * NEMBD);
        int rem = idx - b * ((KK - 1) * NEMBD);
        int k = rem >> 10;
        int e = rem & (NEMBD - 1);
        size_t base = ((size_t)(b * KK + k)) * NEMBD + e;
        float d = g_newx[base] - g_newx[base + NEMBD];
        s += d * d;
    }
    red[threadIdx.x] = s;
    __syncthreads();
    for (int off = 128; off > 0; off >>= 1) {
        if (threadIdx.x < off) red[threadIdx.x] += red[threadIdx.x + off];
        __syncthreads();
    }
    if (threadIdx.x == 0) atomicAdd(&g_acc[1], (double)red[0]);
}

// ---------------------------------------------------------------------------
__global__ void finalize_kernel(float* out, long long loss_idx) {
    double loss = g_acc[0] / (double)PRED_ROWS + g_acc[1] / (double)EMB_ELEMS;
    out[loss_idx] = (float)loss;
}

// ---------------------------------------------------------------------------
extern "C" void kernel_launch(void* const* d_in, const int* in_sizes, int n_in,
                              void* d_out, int out_size) {
    const float* noise       = (const float*)d_in[0];
    const float* left_noise  = (const float*)d_in[1];
    const float* right_noise = (const float*)d_in[2];
    const float* wte         = (const float*)d_in[3];
    const float* wpe         = (const float*)d_in[4];
    const float* W_bb        = (const float*)d_in[5];
    const int*   toks        = (const int*)d_in[6];
    float* out = (float*)d_out;

    static int smem_set = 0;
    if (!smem_set) {
        cudaFuncSetAttribute(gemm1_mma_kernel,
                             cudaFuncAttributeMaxDynamicSharedMemorySize, MMA_SMEM);
        cudaFuncSetAttribute(gemm2_mma_kernel,
                             cudaFuncAttributeMaxDynamicSharedMemorySize, MMA_SMEM);
        smem_set = 1;
    }

    zero_kernel<<<MROWS / 256, 256>>>();

    build_x_kernel<<<(MROWS * NEMBD) / 256, 256>>>(noise, left_noise, right_noise,
                                                   wte, wpe, toks);
    conv_W_kernel<<<dim3(32, 32), 256>>>(W_bb);
    conv_wte_kernel<<<(VPAD * DSTEP) / 256, 256>>>(wte);

    gemm1_mma_kernel<<<dim3(NEMBD / 128, MROWS / 128), 256, MMA_SMEM>>>();

    gemm2_mma_kernel<<<dim3(VPAD / 128, MROWS / 128), 256, MMA_SMEM>>>(out);

    nll_kernel<<<(PRED_ROWS + 255) / 256, 256>>>(out, toks);

    emb_loss_kernel<<<2048, 256>>>();

    long long nlog = (long long)MROWS * VOCAB;
    if ((long long)out_size > nlog) {
        finalize_kernel<<<1, 1>>>(out, (long long)out_size - 1);
    }
}